// round 10
// baseline (speedup 1.0000x reference)
#include <cuda_runtime.h>

#define NT 256
#define PADL 4

// SMEM arena (float offsets). Phase lifetimes:
//  B: writes a1(0..4128), d1(4128..8232)
//  C: reads d1 -> band3 gmem (d1 dead after)
//  D: reads a1 -> writes a2e(4128),a2o(5168),d2(6208..8268)  (a1 dead after)
//  E: reads d2 -> band2 gmem || reads a2 -> writes a3(0),d3(1040) (a2,d2 dead after)
//  F: reads a3,d3 -> writes s1(4128),s0(6208)
//  G: reads s1 -> band1 gmem || reads s0 -> band0 gmem
#define OFF_A1E  0      // 2064
#define OFF_A1O  2064   // 2064
#define OFF_D1   4128   // 4104
#define OFF_A2E  4128   // 1040 (over dead d1)
#define OFF_A2O  5168   // 1040
#define OFF_D2   6208   // 2060
#define OFF_A3   0      // 1032 (over dead a1)
#define OFF_D3   1040   // 1032
#define OFF_S1   4128   // 2060 (over dead a2)
#define OFF_S0   6208   // 2060 (over dead d2)
#define ARENA    8268   // 33072 B -> 6 CTAs/SM

__device__ __forceinline__ float gload(const float* __restrict__ x, int t) {
    t = (t < 0) ? -t : t;
    t = (t >= 8192) ? (16382 - t) : t;
    return x[t];
}

// Level-1 analysis from gmem: x -> a1 split(+pads) + d1 contig. M=4100, G=1025.
__device__ __forceinline__ void analysis_l1(const float* __restrict__ xr,
                                            float* __restrict__ ae, float* __restrict__ ao,
                                            float* __restrict__ hic)
{
    const float WL[8] = {-0.0105974018f, 0.0328830117f, 0.0308413818f, -0.1870348117f,
                         -0.0279837694f, 0.6308807679f, 0.7148465706f,  0.2303778133f};
    const float WH[8] = {-0.2303778133f, 0.7148465706f, -0.6308807679f, -0.0279837694f,
                          0.1870348117f, 0.0308413818f, -0.0328830117f, -0.0105974018f};
    const int M = 4100, G = 1025, LeN = 2050;
    for (int g = threadIdx.x; g < G; g += NT) {
        float v[16];
        if (g >= 1 && g <= G - 2) {
            const float4* p = reinterpret_cast<const float4*>(xr + 8 * g - 8);
            float4 q0 = p[0], q1 = p[1], q2 = p[2], q3 = p[3];
            v[0]=q0.x; v[1]=q0.y; v[2]=q0.z; v[3]=q0.w;
            v[4]=q1.x; v[5]=q1.y; v[6]=q1.z; v[7]=q1.w;
            v[8]=q2.x; v[9]=q2.y; v[10]=q2.z; v[11]=q2.w;
            v[12]=q3.x; v[13]=q3.y; v[14]=q3.z; v[15]=q3.w;
        } else {
            #pragma unroll
            for (int j = 0; j < 16; j++) v[j] = gload(xr, 8 * g - 8 + j);
        }
        float lo[4], hi[4];
        #pragma unroll
        for (int r = 0; r < 4; r++) {
            float accl = WL[0] * v[2*r+1], acch = WH[0] * v[2*r+1];
            #pragma unroll
            for (int k = 1; k < 8; k++) {
                accl = fmaf(WL[k], v[2*r+1+k], accl);
                acch = fmaf(WH[k], v[2*r+1+k], acch);
            }
            lo[r] = accl; hi[r] = acch;
        }
        *reinterpret_cast<float4*>(hic + 4 * g) = make_float4(hi[0], hi[1], hi[2], hi[3]);
        *reinterpret_cast<float2*>(ae + 2 * g) = make_float2(lo[0], lo[2]);
        *reinterpret_cast<float2*>(ao + 2 * g) = make_float2(lo[1], lo[3]);
        if (g < 3 || g > G - 6) {   // mirrored pads for next level
            #pragma unroll
            for (int r = 0; r < 4; r++) {
                const int m = 4 * g + r;
                if (m >= 1 && m <= 8) {
                    if (m & 1) ao[-((m + 1) >> 1)] = lo[r];
                    else       ae[-(m >> 1)]       = lo[r];
                }
                if (m >= M - 17 && m <= M - 2) {
                    if (m & 1) ao[LeN + ((M - 3 - m) >> 1)] = lo[r];
                    else       ae[LeN + ((M - 2 - m) >> 1)] = lo[r];
                }
            }
        }
    }
}

// Split-input analysis for levels 2/3.
template<bool SPLIT>
__device__ __forceinline__ void analysis_v(
    const float* __restrict__ xe, const float* __restrict__ xo, int M,
    float* __restrict__ ae, float* __restrict__ ao, int LeN,
    float* __restrict__ loc, float* __restrict__ hic)
{
    const float A0=-0.0105974018f, A1= 0.0308413818f, A2=-0.0279837694f, A3= 0.7148465706f;
    const float B0= 0.0328830117f, B1=-0.1870348117f, B2= 0.6308807679f, B3= 0.2303778133f;
    const float C0=-0.2303778133f, C1=-0.6308807679f, C2= 0.1870348117f, C3=-0.0328830117f;
    const float E0= 0.7148465706f, E1=-0.0279837694f, E2= 0.0308413818f, E3=-0.0105974018f;
    const int G = (M + 3) >> 2;
    for (int g = threadIdx.x; g < G; g += NT) {
        const int m0 = 4 * g;
        float4 oa = *reinterpret_cast<const float4*>(xo + 4*g - 4);
        float4 ob = *reinterpret_cast<const float4*>(xo + 4*g);
        float4 ea = *reinterpret_cast<const float4*>(xe + 4*g - 4);
        float4 eb = *reinterpret_cast<const float4*>(xe + 4*g);
        float ov[8] = {oa.x,oa.y,oa.z,oa.w,ob.x,ob.y,ob.z,ob.w};
        float ev[8] = {ea.x,ea.y,ea.z,ea.w,eb.x,eb.y,eb.z,eb.w};
        float lo[4], hi[4];
        #pragma unroll
        for (int r = 0; r < 4; r++) {
            lo[r] = fmaf(A0, ov[r], fmaf(A1, ov[r+1], fmaf(A2, ov[r+2], fmaf(A3, ov[r+3],
                    fmaf(B0, ev[r+1], fmaf(B1, ev[r+2], fmaf(B2, ev[r+3], B3*ev[r+4])))))));
            hi[r] = fmaf(C0, ov[r], fmaf(C1, ov[r+1], fmaf(C2, ov[r+2], fmaf(C3, ov[r+3],
                    fmaf(E0, ev[r+1], fmaf(E1, ev[r+2], fmaf(E2, ev[r+3], E3*ev[r+4])))))));
        }
        if (m0 + 3 < M) {
            *reinterpret_cast<float4*>(hic + m0) = make_float4(hi[0],hi[1],hi[2],hi[3]);
            if (SPLIT) {
                *reinterpret_cast<float2*>(ae + 2*g) = make_float2(lo[0], lo[2]);
                *reinterpret_cast<float2*>(ao + 2*g) = make_float2(lo[1], lo[3]);
            } else {
                *reinterpret_cast<float4*>(loc + m0) = make_float4(lo[0],lo[1],lo[2],lo[3]);
            }
        } else {
            #pragma unroll
            for (int r = 0; r < 4; r++) if (m0 + r < M) {
                hic[m0+r] = hi[r];
                if (SPLIT) { int m = m0 + r; if (m & 1) ao[m>>1] = lo[r]; else ae[m>>1] = lo[r]; }
                else loc[m0+r] = lo[r];
            }
        }
        if (SPLIT && (g < 3 || m0 + 3 >= M - 17)) {
            #pragma unroll
            for (int r = 0; r < 4; r++) {
                const int m = m0 + r;
                if (m >= 1 && m <= 8) {
                    if (m & 1) ao[-((m+1)>>1)] = lo[r];
                    else       ae[-(m>>1)]     = lo[r];
                }
                if (m >= M-17 && m <= M-2) {
                    if (m & 1) ao[LeN + ((M-3-m)>>1)] = lo[r];
                    else       ae[LeN + ((M-2-m)>>1)] = lo[r];
                }
            }
        }
    }
}

// Transpose-conv stride2 + crop7, 8 thread-contiguous outputs per thread.
// out[8k+2h]   = w7*in[4k+h]   + w5*in[4k+h+1] + w3*in[4k+h+2] + w1*in[4k+h+3]
// out[8k+2h+1] = w6*in[4k+h+1] + w4*in[4k+h+2] + w2*in[4k+h+3] + w0*in[4k+h+4]
template<bool HIF>
__device__ __forceinline__ void synth8(const float* __restrict__ in, int Lin, float* __restrict__ out)
{
    const float w0 = HIF ? -0.0105974018f :  0.2303778133f;
    const float w1 = HIF ? -0.0328830117f :  0.7148465706f;
    const float w2 = HIF ?  0.0308413818f :  0.6308807679f;
    const float w3 = HIF ?  0.1870348117f : -0.0279837694f;
    const float w4 = HIF ? -0.0279837694f : -0.1870348117f;
    const float w5 = HIF ? -0.6308807679f :  0.0308413818f;
    const float w6 = HIF ?  0.7148465706f :  0.0328830117f;
    const float w7 = HIF ? -0.2303778133f : -0.0105974018f;
    const int Lout = 2 * Lin - 8;
    const int NG = Lout >> 3;
    float4* o4 = reinterpret_cast<float4*>(out);
    for (int k = threadIdx.x; k < NG; k += NT) {
        float4 A = *reinterpret_cast<const float4*>(in + 4*k);
        float4 B = *reinterpret_cast<const float4*>(in + 4*k + 4);
        float v0=A.x, v1=A.y, v2=A.z, v3=A.w, v4=B.x, v5=B.y, v6=B.z, v7=B.w;
        float4 o0, o1;
        o0.x = fmaf(w7, v0, fmaf(w5, v1, fmaf(w3, v2, w1 * v3)));
        o0.y = fmaf(w6, v1, fmaf(w4, v2, fmaf(w2, v3, w0 * v4)));
        o0.z = fmaf(w7, v1, fmaf(w5, v2, fmaf(w3, v3, w1 * v4)));
        o0.w = fmaf(w6, v2, fmaf(w4, v3, fmaf(w2, v4, w0 * v5)));
        o1.x = fmaf(w7, v2, fmaf(w5, v3, fmaf(w3, v4, w1 * v5)));
        o1.y = fmaf(w6, v3, fmaf(w4, v4, fmaf(w2, v5, w0 * v6)));
        o1.z = fmaf(w7, v3, fmaf(w5, v4, fmaf(w3, v5, w1 * v6)));
        o1.w = fmaf(w6, v4, fmaf(w4, v5, fmaf(w2, v6, w0 * v7)));
        o4[2*k] = o0; o4[2*k+1] = o1;
    }
    const int rem = Lout & 7;     // 0 or 6 in our shapes
    if (rem && threadIdx.x < rem) {
        const int p = (NG << 3) + threadIdx.x;
        const int q = p >> 1;
        float r;
        if ((p & 1) == 0)
            r = fmaf(w7, in[q],   fmaf(w5, in[q+1], fmaf(w3, in[q+2], w1 * in[q+3])));
        else
            r = fmaf(w6, in[q+1], fmaf(w4, in[q+2], fmaf(w2, in[q+3], w0 * in[q+4])));
        out[p] = r;
    }
}

// Fused double synth: outer LO ∘ inner<INNER_HIF>, in[2054] smem -> out[8192] gmem.
// 8 outputs/thread: T[0..7]=inner[4k..4k+7] from in[2k..2k+7] (4x LDS.64), 2x STG.128.
template<bool INNER_HIF>
__device__ __forceinline__ void fused2g8(const float* __restrict__ in, float* __restrict__ out)
{
    const float i0 = INNER_HIF ? -0.0105974018f :  0.2303778133f;
    const float i1 = INNER_HIF ? -0.0328830117f :  0.7148465706f;
    const float i2 = INNER_HIF ?  0.0308413818f :  0.6308807679f;
    const float i3 = INNER_HIF ?  0.1870348117f : -0.0279837694f;
    const float i4 = INNER_HIF ? -0.0279837694f : -0.1870348117f;
    const float i5 = INNER_HIF ? -0.6308807679f :  0.0308413818f;
    const float i6 = INNER_HIF ?  0.7148465706f :  0.0328830117f;
    const float i7 = INNER_HIF ? -0.2303778133f : -0.0105974018f;
    const float L0 =  0.2303778133f, L1 =  0.7148465706f, L2 =  0.6308807679f, L3 = -0.0279837694f;
    const float L4 = -0.1870348117f, L5 =  0.0308413818f, L6 =  0.0328830117f, L7 = -0.0105974018f;
    float4* o4 = reinterpret_cast<float4*>(out);
    for (int k = threadIdx.x; k < 1024; k += NT) {
        float2 a = *reinterpret_cast<const float2*>(in + 2*k);
        float2 b = *reinterpret_cast<const float2*>(in + 2*k + 2);
        float2 c = *reinterpret_cast<const float2*>(in + 2*k + 4);
        float2 d = *reinterpret_cast<const float2*>(in + 2*k + 6);
        float v[8] = {a.x, a.y, b.x, b.y, c.x, c.y, d.x, d.y};
        float T[8];
        #pragma unroll
        for (int l = 0; l < 4; l++) {
            T[2*l]   = fmaf(i7, v[l],   fmaf(i5, v[l+1], fmaf(i3, v[l+2], i1 * v[l+3])));
            T[2*l+1] = fmaf(i6, v[l+1], fmaf(i4, v[l+2], fmaf(i2, v[l+3], i0 * v[l+4])));
        }
        float4 o0, o1;
        o0.x = fmaf(L7, T[0], fmaf(L5, T[1], fmaf(L3, T[2], L1 * T[3])));
        o0.y = fmaf(L6, T[1], fmaf(L4, T[2], fmaf(L2, T[3], L0 * T[4])));
        o0.z = fmaf(L7, T[1], fmaf(L5, T[2], fmaf(L3, T[3], L1 * T[4])));
        o0.w = fmaf(L6, T[2], fmaf(L4, T[3], fmaf(L2, T[4], L0 * T[5])));
        o1.x = fmaf(L7, T[2], fmaf(L5, T[3], fmaf(L3, T[4], L1 * T[5])));
        o1.y = fmaf(L6, T[3], fmaf(L4, T[4], fmaf(L2, T[5], L0 * T[6])));
        o1.z = fmaf(L7, T[3], fmaf(L5, T[4], fmaf(L3, T[5], L1 * T[6])));
        o1.w = fmaf(L6, T[4], fmaf(L4, T[5], fmaf(L2, T[6], L0 * T[7])));
        o4[2*k] = o0; o4[2*k+1] = o1;
    }
}

__global__ void __launch_bounds__(NT, 6)
dwt_kernel(const float* __restrict__ x, float* __restrict__ out)
{
    extern __shared__ float s[];
    const int row = blockIdx.x;                  // 0..2047
    const float* __restrict__ xr = x + (size_t)row * 8192;

    float* a1e = s + OFF_A1E + PADL;  float* a1o = s + OFF_A1O + PADL;
    float* a2e = s + OFF_A2E + PADL;  float* a2o = s + OFF_A2O + PADL;
    float* d1 = s + OFF_D1;  float* d2 = s + OFF_D2;  float* d3 = s + OFF_D3;
    float* a3 = s + OFF_A3;  float* s1 = s + OFF_S1;  float* s0 = s + OFF_S0;

    // B: level-1 analysis from gmem: x -> a1(split,+pads), d1
    analysis_l1(xr, a1e, a1o, d1);
    __syncthreads();

    // C: band3 = HI-synth(d1) -> gmem (coalesced float4)
    synth8<true>(d1, 4100, out + ((size_t)(3*2048 + row)) * 8192);
    __syncthreads();

    // D: level-2 analysis: a1 -> a2(split,+pads), d2   (a2/d2 overlay dead d1)
    analysis_v<true>(a1e, a1o, 2054, a2e, a2o, 1027, nullptr, d2);
    __syncthreads();

    // E: band2 = LO∘HI fused (d2 -> gmem) || level-3: a2 -> a3, d3 (over dead a1)
    fused2g8<true>(d2, out + ((size_t)(2*2048 + row)) * 8192);
    analysis_v<false>(a2e, a2o, 1031, nullptr, nullptr, 0, a3, d3);
    __syncthreads();

    // F: s1 = HI-synth(d3) || s0 = LO-synth(a3)   (s1/s0 overlay dead a2/d2)
    synth8<true>(d3, 1031, s1);
    synth8<false>(a3, 1031, s0);
    __syncthreads();

    // G: band1 = LO∘LO fused (s1 -> gmem) || band0 = LO∘LO fused (s0 -> gmem)
    fused2g8<false>(s1, out + ((size_t)(1*2048 + row)) * 8192);
    fused2g8<false>(s0, out + (size_t)row * 8192);
}

extern "C" void kernel_launch(void* const* d_in, const int* in_sizes, int n_in,
                              void* d_out, int out_size)
{
    const float* x = (const float*)d_in[0];
    float* out = (float*)d_out;
    cudaFuncSetAttribute(dwt_kernel, cudaFuncAttributeMaxDynamicSharedMemorySize,
                         ARENA * (int)sizeof(float));
    dwt_kernel<<<2048, NT, ARENA * sizeof(float)>>>(x, out);
}

// round 16
// speedup vs baseline: 1.0051x; 1.0051x over previous
#include <cuda_runtime.h>

#define NT 256
#define PADL 4

// SMEM arena (float offsets) — R8 layout (overlap phases), lifetimes:
#define OFF_A1E  0      // 2064                 live B..C
#define OFF_A1O  2064   // 2064                 live B..C
#define OFF_D1   4128   // 4104                 live B..C
#define OFF_A2E  8232   // 1040                 live C..D
#define OFF_A2O  9272   // 1040                 live C..D
#define OFF_D2   10312  // 2056 -> 12368        live C..D
#define OFF_A3   0      // 1032 (over dead a1)  live D..E
#define OFF_D3   1032   // 1032 (over dead a1)  live D..E
#define OFF_S1   4128   // 2056 (over dead d1)  live E..F
#define OFF_S0   6188   // 2056 (over dead d1)  live E..F
#define ARENA    12368  // 49472 B -> 4 CTAs/SM

__device__ __forceinline__ float gload(const float* __restrict__ x, int t) {
    t = (t < 0) ? -t : t;
    t = (t >= 8192) ? (16382 - t) : t;
    return x[t];
}

// Level-1 analysis from gmem: x -> a1 split(+pads) + d1 contig. M=4100, G=1025.
__device__ __forceinline__ void analysis_l1(const float* __restrict__ xr,
                                            float* __restrict__ ae, float* __restrict__ ao,
                                            float* __restrict__ hic)
{
    const float WL[8] = {-0.0105974018f, 0.0328830117f, 0.0308413818f, -0.1870348117f,
                         -0.0279837694f, 0.6308807679f, 0.7148465706f,  0.2303778133f};
    const float WH[8] = {-0.2303778133f, 0.7148465706f, -0.6308807679f, -0.0279837694f,
                          0.1870348117f, 0.0308413818f, -0.0328830117f, -0.0105974018f};
    const int M = 4100, G = 1025, LeN = 2050;
    for (int g = threadIdx.x; g < G; g += NT) {
        float v[16];
        if (g >= 1 && g <= G - 2) {
            const float4* p = reinterpret_cast<const float4*>(xr + 8 * g - 8);
            float4 q0 = p[0], q1 = p[1], q2 = p[2], q3 = p[3];
            v[0]=q0.x; v[1]=q0.y; v[2]=q0.z; v[3]=q0.w;
            v[4]=q1.x; v[5]=q1.y; v[6]=q1.z; v[7]=q1.w;
            v[8]=q2.x; v[9]=q2.y; v[10]=q2.z; v[11]=q2.w;
            v[12]=q3.x; v[13]=q3.y; v[14]=q3.z; v[15]=q3.w;
        } else {
            #pragma unroll
            for (int j = 0; j < 16; j++) v[j] = gload(xr, 8 * g - 8 + j);
        }
        float lo[4], hi[4];
        #pragma unroll
        for (int r = 0; r < 4; r++) {
            float accl = WL[0] * v[2*r+1], acch = WH[0] * v[2*r+1];
            #pragma unroll
            for (int k = 1; k < 8; k++) {
                accl = fmaf(WL[k], v[2*r+1+k], accl);
                acch = fmaf(WH[k], v[2*r+1+k], acch);
            }
            lo[r] = accl; hi[r] = acch;
        }
        *reinterpret_cast<float4*>(hic + 4 * g) = make_float4(hi[0], hi[1], hi[2], hi[3]);
        *reinterpret_cast<float2*>(ae + 2 * g) = make_float2(lo[0], lo[2]);
        *reinterpret_cast<float2*>(ao + 2 * g) = make_float2(lo[1], lo[3]);
        if (g < 3 || g > G - 6) {   // mirrored pads for next level
            #pragma unroll
            for (int r = 0; r < 4; r++) {
                const int m = 4 * g + r;
                if (m >= 1 && m <= 8) {
                    if (m & 1) ao[-((m + 1) >> 1)] = lo[r];
                    else       ae[-(m >> 1)]       = lo[r];
                }
                if (m >= M - 17 && m <= M - 2) {
                    if (m & 1) ao[LeN + ((M - 3 - m) >> 1)] = lo[r];
                    else       ae[LeN + ((M - 2 - m) >> 1)] = lo[r];
                }
            }
        }
    }
}

// Split-input analysis for levels 2/3.
template<bool SPLIT>
__device__ __forceinline__ void analysis_v(
    const float* __restrict__ xe, const float* __restrict__ xo, int M,
    float* __restrict__ ae, float* __restrict__ ao, int LeN,
    float* __restrict__ loc, float* __restrict__ hic)
{
    const float A0=-0.0105974018f, A1= 0.0308413818f, A2=-0.0279837694f, A3= 0.7148465706f;
    const float B0= 0.0328830117f, B1=-0.1870348117f, B2= 0.6308807679f, B3= 0.2303778133f;
    const float C0=-0.2303778133f, C1=-0.6308807679f, C2= 0.1870348117f, C3=-0.0328830117f;
    const float E0= 0.7148465706f, E1=-0.0279837694f, E2= 0.0308413818f, E3=-0.0105974018f;
    const int G = (M + 3) >> 2;
    for (int g = threadIdx.x; g < G; g += NT) {
        const int m0 = 4 * g;
        float4 oa = *reinterpret_cast<const float4*>(xo + 4*g - 4);
        float4 ob = *reinterpret_cast<const float4*>(xo + 4*g);
        float4 ea = *reinterpret_cast<const float4*>(xe + 4*g - 4);
        float4 eb = *reinterpret_cast<const float4*>(xe + 4*g);
        float ov[8] = {oa.x,oa.y,oa.z,oa.w,ob.x,ob.y,ob.z,ob.w};
        float ev[8] = {ea.x,ea.y,ea.z,ea.w,eb.x,eb.y,eb.z,eb.w};
        float lo[4], hi[4];
        #pragma unroll
        for (int r = 0; r < 4; r++) {
            lo[r] = fmaf(A0, ov[r], fmaf(A1, ov[r+1], fmaf(A2, ov[r+2], fmaf(A3, ov[r+3],
                    fmaf(B0, ev[r+1], fmaf(B1, ev[r+2], fmaf(B2, ev[r+3], B3*ev[r+4])))))));
            hi[r] = fmaf(C0, ov[r], fmaf(C1, ov[r+1], fmaf(C2, ov[r+2], fmaf(C3, ov[r+3],
                    fmaf(E0, ev[r+1], fmaf(E1, ev[r+2], fmaf(E2, ev[r+3], E3*ev[r+4])))))));
        }
        if (m0 + 3 < M) {
            *reinterpret_cast<float4*>(hic + m0) = make_float4(hi[0],hi[1],hi[2],hi[3]);
            if (SPLIT) {
                *reinterpret_cast<float2*>(ae + 2*g) = make_float2(lo[0], lo[2]);
                *reinterpret_cast<float2*>(ao + 2*g) = make_float2(lo[1], lo[3]);
            } else {
                *reinterpret_cast<float4*>(loc + m0) = make_float4(lo[0],lo[1],lo[2],lo[3]);
            }
        } else {
            #pragma unroll
            for (int r = 0; r < 4; r++) if (m0 + r < M) {
                hic[m0+r] = hi[r];
                if (SPLIT) { int m = m0 + r; if (m & 1) ao[m>>1] = lo[r]; else ae[m>>1] = lo[r]; }
                else loc[m0+r] = lo[r];
            }
        }
        if (SPLIT && (g < 3 || m0 + 3 >= M - 17)) {
            #pragma unroll
            for (int r = 0; r < 4; r++) {
                const int m = m0 + r;
                if (m >= 1 && m <= 8) {
                    if (m & 1) ao[-((m+1)>>1)] = lo[r];
                    else       ae[-(m>>1)]     = lo[r];
                }
                if (m >= M-17 && m <= M-2) {
                    if (m & 1) ao[LeN + ((M-3-m)>>1)] = lo[r];
                    else       ae[LeN + ((M-2-m)>>1)] = lo[r];
                }
            }
        }
    }
}

// Transpose-conv stride2 + crop7, 8 thread-contiguous outputs per thread.
// out[8k+2h]   = w7*in[4k+h]   + w5*in[4k+h+1] + w3*in[4k+h+2] + w1*in[4k+h+3]
// out[8k+2h+1] = w6*in[4k+h+1] + w4*in[4k+h+2] + w2*in[4k+h+3] + w0*in[4k+h+4]
template<bool HIF>
__device__ __forceinline__ void synth8(const float* __restrict__ in, int Lin, float* __restrict__ out)
{
    const float w0 = HIF ? -0.0105974018f :  0.2303778133f;
    const float w1 = HIF ? -0.0328830117f :  0.7148465706f;
    const float w2 = HIF ?  0.0308413818f :  0.6308807679f;
    const float w3 = HIF ?  0.1870348117f : -0.0279837694f;
    const float w4 = HIF ? -0.0279837694f : -0.1870348117f;
    const float w5 = HIF ? -0.6308807679f :  0.0308413818f;
    const float w6 = HIF ?  0.7148465706f :  0.0328830117f;
    const float w7 = HIF ? -0.2303778133f : -0.0105974018f;
    const int Lout = 2 * Lin - 8;
    const int NG = Lout >> 3;
    float4* o4 = reinterpret_cast<float4*>(out);
    for (int k = threadIdx.x; k < NG; k += NT) {
        float4 A = *reinterpret_cast<const float4*>(in + 4*k);
        float4 B = *reinterpret_cast<const float4*>(in + 4*k + 4);
        float v0=A.x, v1=A.y, v2=A.z, v3=A.w, v4=B.x, v5=B.y, v6=B.z, v7=B.w;
        float4 o0, o1;
        o0.x = fmaf(w7, v0, fmaf(w5, v1, fmaf(w3, v2, w1 * v3)));
        o0.y = fmaf(w6, v1, fmaf(w4, v2, fmaf(w2, v3, w0 * v4)));
        o0.z = fmaf(w7, v1, fmaf(w5, v2, fmaf(w3, v3, w1 * v4)));
        o0.w = fmaf(w6, v2, fmaf(w4, v3, fmaf(w2, v4, w0 * v5)));
        o1.x = fmaf(w7, v2, fmaf(w5, v3, fmaf(w3, v4, w1 * v5)));
        o1.y = fmaf(w6, v3, fmaf(w4, v4, fmaf(w2, v5, w0 * v6)));
        o1.z = fmaf(w7, v3, fmaf(w5, v4, fmaf(w3, v5, w1 * v6)));
        o1.w = fmaf(w6, v4, fmaf(w4, v5, fmaf(w2, v6, w0 * v7)));
        o4[2*k] = o0; o4[2*k+1] = o1;
    }
    const int rem = Lout & 7;     // 0 or 6 in our shapes
    if (rem && threadIdx.x < rem) {
        const int p = (NG << 3) + threadIdx.x;
        const int q = p >> 1;
        float r;
        if ((p & 1) == 0)
            r = fmaf(w7, in[q],   fmaf(w5, in[q+1], fmaf(w3, in[q+2], w1 * in[q+3])));
        else
            r = fmaf(w6, in[q+1], fmaf(w4, in[q+2], fmaf(w2, in[q+3], w0 * in[q+4])));
        out[p] = r;
    }
}

// Fused double synth: outer LO ∘ inner<INNER_HIF>, in[2054] smem -> out[8192] gmem.
// 8 outputs/thread: T[0..7]=inner[4k..4k+7] from in[2k..2k+7] (4x LDS.64), 2x STG.128.
template<bool INNER_HIF>
__device__ __forceinline__ void fused2g8(const float* __restrict__ in, float* __restrict__ out)
{
    const float i0 = INNER_HIF ? -0.0105974018f :  0.2303778133f;
    const float i1 = INNER_HIF ? -0.0328830117f :  0.7148465706f;
    const float i2 = INNER_HIF ?  0.0308413818f :  0.6308807679f;
    const float i3 = INNER_HIF ?  0.1870348117f : -0.0279837694f;
    const float i4 = INNER_HIF ? -0.0279837694f : -0.1870348117f;
    const float i5 = INNER_HIF ? -0.6308807679f :  0.0308413818f;
    const float i6 = INNER_HIF ?  0.7148465706f :  0.0328830117f;
    const float i7 = INNER_HIF ? -0.2303778133f : -0.0105974018f;
    const float L0 =  0.2303778133f, L1 =  0.7148465706f, L2 =  0.6308807679f, L3 = -0.0279837694f;
    const float L4 = -0.1870348117f, L5 =  0.0308413818f, L6 =  0.0328830117f, L7 = -0.0105974018f;
    float4* o4 = reinterpret_cast<float4*>(out);
    for (int k = threadIdx.x; k < 1024; k += NT) {
        float2 a = *reinterpret_cast<const float2*>(in + 2*k);
        float2 b = *reinterpret_cast<const float2*>(in + 2*k + 2);
        float2 c = *reinterpret_cast<const float2*>(in + 2*k + 4);
        float2 d = *reinterpret_cast<const float2*>(in + 2*k + 6);
        float v[8] = {a.x, a.y, b.x, b.y, c.x, c.y, d.x, d.y};
        float T[8];
        #pragma unroll
        for (int l = 0; l < 4; l++) {
            T[2*l]   = fmaf(i7, v[l],   fmaf(i5, v[l+1], fmaf(i3, v[l+2], i1 * v[l+3])));
            T[2*l+1] = fmaf(i6, v[l+1], fmaf(i4, v[l+2], fmaf(i2, v[l+3], i0 * v[l+4])));
        }
        float4 o0, o1;
        o0.x = fmaf(L7, T[0], fmaf(L5, T[1], fmaf(L3, T[2], L1 * T[3])));
        o0.y = fmaf(L6, T[1], fmaf(L4, T[2], fmaf(L2, T[3], L0 * T[4])));
        o0.z = fmaf(L7, T[1], fmaf(L5, T[2], fmaf(L3, T[3], L1 * T[4])));
        o0.w = fmaf(L6, T[2], fmaf(L4, T[3], fmaf(L2, T[4], L0 * T[5])));
        o1.x = fmaf(L7, T[2], fmaf(L5, T[3], fmaf(L3, T[4], L1 * T[5])));
        o1.y = fmaf(L6, T[3], fmaf(L4, T[4], fmaf(L2, T[5], L0 * T[6])));
        o1.z = fmaf(L7, T[3], fmaf(L5, T[4], fmaf(L3, T[5], L1 * T[6])));
        o1.w = fmaf(L6, T[4], fmaf(L4, T[5], fmaf(L2, T[6], L0 * T[7])));
        o4[2*k] = o0; o4[2*k+1] = o1;
    }
}

__global__ void __launch_bounds__(NT, 4)
dwt_kernel(const float* __restrict__ x, float* __restrict__ out)
{
    extern __shared__ float s[];
    const int row = blockIdx.x;                  // 0..2047
    const float* __restrict__ xr = x + (size_t)row * 8192;

    float* a1e = s + OFF_A1E + PADL;  float* a1o = s + OFF_A1O + PADL;
    float* a2e = s + OFF_A2E + PADL;  float* a2o = s + OFF_A2O + PADL;
    float* d1 = s + OFF_D1;  float* d2 = s + OFF_D2;  float* d3 = s + OFF_D3;
    float* a3 = s + OFF_A3;  float* s1 = s + OFF_S1;  float* s0 = s + OFF_S0;

    // B: level-1 analysis from gmem: x -> a1(split,+pads), d1
    analysis_l1(xr, a1e, a1o, d1);
    __syncthreads();

    // C: band3 = HI-synth(d1) -> gmem  ||  level-2: a1 -> a2(split,+pads), d2
    synth8<true>(d1, 4100, out + ((size_t)(3*2048 + row)) * 8192);
    analysis_v<true>(a1e, a1o, 2054, a2e, a2o, 1027, nullptr, d2);
    __syncthreads();

    // D: band2 = LO∘HI fused (d2 -> gmem)  ||  level-3: a2 -> a3, d3 (over dead a1)
    fused2g8<true>(d2, out + ((size_t)(2*2048 + row)) * 8192);
    analysis_v<false>(a2e, a2o, 1031, nullptr, nullptr, 0, a3, d3);
    __syncthreads();

    // E: s1 = HI-synth(d3)  ||  s0 = LO-synth(a3)   (s1/s0 overlay dead d1 region)
    synth8<true>(d3, 1031, s1);
    synth8<false>(a3, 1031, s0);
    __syncthreads();

    // F: band1 = LO∘LO fused (s1 -> gmem)  ||  band0 = LO∘LO fused (s0 -> gmem)
    fused2g8<false>(s1, out + ((size_t)(1*2048 + row)) * 8192);
    fused2g8<false>(s0, out + (size_t)row * 8192);
}

extern "C" void kernel_launch(void* const* d_in, const int* in_sizes, int n_in,
                              void* d_out, int out_size)
{
    const float* x = (const float*)d_in[0];
    float* out = (float*)d_out;
    cudaFuncSetAttribute(dwt_kernel, cudaFuncAttributeMaxDynamicSharedMemorySize,
                         ARENA * (int)sizeof(float));
    dwt_kernel<<<2048, NT, ARENA * sizeof(float)>>>(x, out);
}